// round 8
// baseline (speedup 1.0000x reference)
#include <cuda_runtime.h>
#include <cstdint>
#include <cstddef>

#define NROWS 16384
#define DM    1024
#define DF    4096

#define BM 128
#define BN 256
#define BK 32
#define NBUF 4
#define A_BYTES (BM * BK * 4)           // 16384
#define B_BYTES (BN * BK * 4)           // 32768
#define STAGE_BYTES (A_BYTES + B_BYTES) // 49152
#define SM_STAGE_OFF 1024
#define SMEM_BYTES (SM_STAGE_OFF + NBUF * STAGE_BYTES) // 197632

// Scratch (allocation-free rule: __device__ globals)
__device__ float g_x[(size_t)NROWS * DM];
__device__ float g_w1[(size_t)DF * DM];
__device__ float g_w2[(size_t)DM * DF];
__device__ float g_inner[(size_t)NROWS * DF];
__device__ float g_part[(size_t)4 * NROWS];

static __device__ __forceinline__ uint32_t smem_u32(const void* p) {
    uint32_t a;
    asm("{ .reg .u64 t; cvta.to.shared.u64 t, %1; cvt.u32.u64 %0, t; }" : "=r"(a) : "l"(p));
    return a;
}
static __device__ __forceinline__ void cp16(uint32_t dst, const void* src) {
    asm volatile("cp.async.cg.shared.global [%0], [%1], 16;" :: "r"(dst), "l"(src) : "memory");
}
static __device__ __forceinline__ void cp_commit() {
    asm volatile("cp.async.commit_group;" ::: "memory");
}
static __device__ __forceinline__ void cp_wait2() {
    asm volatile("cp.async.wait_group 2;" ::: "memory");
}
static __device__ __forceinline__ float rna_tf32(float v) {
    uint32_t u;
    asm("cvt.rna.tf32.f32 %0, %1;" : "=r"(u) : "f"(v));
    return __uint_as_float(u);
}
static __device__ __forceinline__ void ldsm_x4(uint32_t* r, uint32_t addr) {
    asm volatile("ldmatrix.sync.aligned.m8n8.x4.shared.b16 {%0,%1,%2,%3}, [%4];"
                 : "=r"(r[0]), "=r"(r[1]), "=r"(r[2]), "=r"(r[3]) : "r"(addr));
}
static __device__ __forceinline__ void ldsm_x2(uint32_t* r, uint32_t addr) {
    asm volatile("ldmatrix.sync.aligned.m8n8.x2.shared.b16 {%0,%1}, [%2];"
                 : "=r"(r[0]), "=r"(r[1]) : "r"(addr));
}
static __device__ __forceinline__ void mma_tf32(float* d, const uint32_t* a, const uint32_t* b) {
    asm volatile(
        "mma.sync.aligned.m16n8k8.row.col.f32.tf32.tf32.f32 "
        "{%0,%1,%2,%3}, {%4,%5,%6,%7}, {%8,%9}, {%0,%1,%2,%3};"
        : "+f"(d[0]), "+f"(d[1]), "+f"(d[2]), "+f"(d[3])
        : "r"(a[0]), "r"(a[1]), "r"(a[2]), "r"(a[3]), "r"(b[0]), "r"(b[1]));
}
static __device__ __forceinline__ float fast_tanh(float x) {
    return 1.0f - 2.0f / (1.0f + __expf(2.0f * x));
}

// Load one k-stage (A: BM x BK, B: BN x BK) into swizzled smem via cp.async. 512 threads.
template <int KD>
static __device__ __forceinline__ void load_stage(char* sm, int buf, const float* A,
                                                  const float* W, int m0, int n0,
                                                  int kt, int tid) {
    char* base = sm + SM_STAGE_OFF + buf * STAGE_BYTES;
    const float* asrc = A + (size_t)m0 * KD + (size_t)kt * BK;
    const float* bsrc = W + (size_t)n0 * KD + (size_t)kt * BK;
#pragma unroll
    for (int j = 0; j < 2; j++) {                       // A: 1024 16B chunks
        int i = tid + j * 512;
        int row = i >> 3, jj = i & 7;
        uint32_t woff = row * 32 + ((jj * 4) ^ ((row & 7) * 4));
        cp16(smem_u32(base + woff * 4), asrc + (size_t)row * KD + jj * 4);
    }
#pragma unroll
    for (int j = 0; j < 4; j++) {                       // B: 2048 16B chunks
        int i = tid + j * 512;
        int row = i >> 3, jj = i & 7;
        uint32_t woff = row * 32 + ((jj * 4) ^ ((row & 7) * 4));
        cp16(smem_u32(base + A_BYTES + woff * 4), bsrc + (size_t)row * KD + jj * 4);
    }
    cp_commit();
}

// MODE 1: g_inner = rna_tf32(tanh(A@W^T + bias)); MODE 2: g_part = rowdot(tanh(...), X)
// 16 warps: warp grid 2 (M) x 8 (N); warp tile 64x32.
template <int KD, int MODE>
__global__ void __launch_bounds__(512, 1)
gemm_kernel(const float* __restrict__ A, const float* __restrict__ W,
            const float* __restrict__ bias, const float* __restrict__ X) {
    extern __shared__ char sm[];
    const int tid = threadIdx.x;
    const int lane = tid & 31;
    const int wid = tid >> 5;
    const int wm = wid & 1;        // 2 warps over M (64 rows each)
    const int wn = wid >> 1;       // 8 warps over N (32 cols each)
    const int r = lane >> 2, c = lane & 3;
    const int m0 = blockIdx.y * BM;
    const int n0 = blockIdx.x * BN;
    const int KT = KD / BK;

    if (tid < 256) ((float*)sm)[tid] = bias[n0 + tid];

    // per-lane ldmatrix address components
    const uint32_t aBase = (uint32_t)(wm * 64 + (lane & 15)) * 128;  // byte offset of lane's A row
    const uint32_t bBase = (uint32_t)(wn * 32 + (lane & 7)) * 128;   // byte offset of lane's B row
    const uint32_t swl = (uint32_t)(lane & 7) << 4;                  // swizzle term (16B units)
    const uint32_t ahalf4 = (uint32_t)(lane >> 4) << 4;              // A k-half select
    const uint32_t bhalf4 = (uint32_t)((lane >> 3) & 1) << 4;        // B k-half select

    float acc[4][4][4];
#pragma unroll
    for (int mt = 0; mt < 4; mt++)
#pragma unroll
        for (int nt = 0; nt < 4; nt++)
#pragma unroll
            for (int q = 0; q < 4; q++) acc[mt][nt][q] = 0.0f;

    load_stage<KD>(sm, 0, A, W, m0, n0, 0, tid);
    load_stage<KD>(sm, 1, A, W, m0, n0, 1, tid);

    for (int kt = 0; kt < KT; kt++) {
        if (kt + 2 < KT) load_stage<KD>(sm, (kt + 2) & 3, A, W, m0, n0, kt + 2, tid);
        else cp_commit();  // keep group accounting uniform
        cp_wait2();
        __syncthreads();

        const uint32_t As = smem_u32(sm + SM_STAGE_OFF + (kt & 3) * STAGE_BYTES);
        const uint32_t Bs = As + A_BYTES;
#pragma unroll
        for (int ks = 0; ks < 4; ks++) {
            uint32_t af[4][4], bf[4][2];
            const uint32_t jxa = ((uint32_t)ks << 5) + ahalf4;   // j*16 for A lanes
            const uint32_t jxb = ((uint32_t)ks << 5) + bhalf4;   // j*16 for B lanes
            const uint32_t aoff = jxa ^ swl;
            const uint32_t boff = jxb ^ swl;
#pragma unroll
            for (int mt = 0; mt < 4; mt++)
                ldsm_x4(af[mt], As + aBase + (uint32_t)mt * 2048 + aoff);
#pragma unroll
            for (int nt = 0; nt < 4; nt++)
                ldsm_x2(bf[nt], Bs + bBase + (uint32_t)nt * 1024 + boff);
#pragma unroll
            for (int mt = 0; mt < 4; mt++)
#pragma unroll
                for (int nt = 0; nt < 4; nt++)
                    mma_tf32(acc[mt][nt], af[mt], bf[nt]);
        }
    }
    __syncthreads();

    const float* bsm = (const float*)sm;
    if (MODE == 1) {
#pragma unroll
        for (int mt = 0; mt < 4; mt++) {
            int row = m0 + wm * 64 + mt * 16 + r;
#pragma unroll
            for (int nt = 0; nt < 4; nt++) {
                int cl = wn * 32 + nt * 8 + c * 2;   // col within tile
                float2 v0, v1;
                v0.x = rna_tf32(fast_tanh(acc[mt][nt][0] + bsm[cl]));
                v0.y = rna_tf32(fast_tanh(acc[mt][nt][1] + bsm[cl + 1]));
                v1.x = rna_tf32(fast_tanh(acc[mt][nt][2] + bsm[cl]));
                v1.y = rna_tf32(fast_tanh(acc[mt][nt][3] + bsm[cl + 1]));
                *(float2*)(g_inner + (size_t)row * DF + n0 + cl) = v0;
                *(float2*)(g_inner + (size_t)(row + 8) * DF + n0 + cl) = v1;
            }
        }
    } else {
        float rowacc[4][2];
#pragma unroll
        for (int mt = 0; mt < 4; mt++) { rowacc[mt][0] = 0.0f; rowacc[mt][1] = 0.0f; }
#pragma unroll
        for (int mt = 0; mt < 4; mt++) {
            int row = m0 + wm * 64 + mt * 16 + r;
#pragma unroll
            for (int nt = 0; nt < 4; nt++) {
                int cl = wn * 32 + nt * 8 + c * 2;
                float2 x0 = *(const float2*)(X + (size_t)row * DM + n0 + cl);
                float2 x1 = *(const float2*)(X + (size_t)(row + 8) * DM + n0 + cl);
                rowacc[mt][0] += fast_tanh(acc[mt][nt][0] + bsm[cl]) * x0.x
                               + fast_tanh(acc[mt][nt][1] + bsm[cl + 1]) * x0.y;
                rowacc[mt][1] += fast_tanh(acc[mt][nt][2] + bsm[cl]) * x1.x
                               + fast_tanh(acc[mt][nt][3] + bsm[cl + 1]) * x1.y;
            }
        }
        // reduce across the 4 lanes sharing a row
#pragma unroll
        for (int mt = 0; mt < 4; mt++)
#pragma unroll
            for (int h = 0; h < 2; h++) {
                float v = rowacc[mt][h];
                v += __shfl_xor_sync(0xFFFFFFFF, v, 1);
                v += __shfl_xor_sync(0xFFFFFFFF, v, 2);
                rowacc[mt][h] = v;
            }
        float* part = (float*)(sm + SM_STAGE_OFF);  // [128][8], stages dead now
        if (c == 0) {
#pragma unroll
            for (int mt = 0; mt < 4; mt++) {
                part[(wm * 64 + mt * 16 + r) * 8 + wn] = rowacc[mt][0];
                part[(wm * 64 + mt * 16 + r + 8) * 8 + wn] = rowacc[mt][1];
            }
        }
        __syncthreads();
        if (tid < 128) {
            float s = 0.0f;
#pragma unroll
            for (int j = 0; j < 8; j++) s += part[tid * 8 + j];
            g_part[(size_t)blockIdx.x * NROWS + m0 + tid] = s;
        }
    }
}

__global__ void roundcopy_kernel(float* __restrict__ dst, const float* __restrict__ src, int n4) {
    int i = blockIdx.x * blockDim.x + threadIdx.x;
    if (i < n4) {
        float4 v = ((const float4*)src)[i];
        v.x = rna_tf32(v.x); v.y = rna_tf32(v.y);
        v.z = rna_tf32(v.z); v.w = rna_tf32(v.w);
        ((float4*)dst)[i] = v;
    }
}

__global__ void finalize_kernel(float* __restrict__ out) {
    int i = blockIdx.x * blockDim.x + threadIdx.x;
    if (i < NROWS) {
        float s = g_part[i] + g_part[NROWS + i] + g_part[2 * NROWS + i] + g_part[3 * NROWS + i];
        out[i] = 1.0f / (1.0f + __expf(-s));
    }
}

extern "C" void kernel_launch(void* const* d_in, const int* in_sizes, int n_in,
                              void* d_out, int out_size) {
    const float* X  = (const float*)d_in[0];
    const float* W1 = (const float*)d_in[1];
    const float* b1 = (const float*)d_in[2];
    const float* W2 = (const float*)d_in[3];
    const float* b2 = (const float*)d_in[4];

    float *px, *pw1, *pw2, *pin;
    cudaGetSymbolAddress((void**)&px,  g_x);
    cudaGetSymbolAddress((void**)&pw1, g_w1);
    cudaGetSymbolAddress((void**)&pw2, g_w2);
    cudaGetSymbolAddress((void**)&pin, g_inner);

    cudaFuncSetAttribute(gemm_kernel<DM, 1>, cudaFuncAttributeMaxDynamicSharedMemorySize, SMEM_BYTES);
    cudaFuncSetAttribute(gemm_kernel<DF, 2>, cudaFuncAttributeMaxDynamicSharedMemorySize, SMEM_BYTES);

    roundcopy_kernel<<<(NROWS * DM / 4 + 255) / 256, 256>>>(px, X, NROWS * DM / 4);
    roundcopy_kernel<<<(DF * DM / 4 + 255) / 256, 256>>>(pw1, W1, DF * DM / 4);
    roundcopy_kernel<<<(DM * DF / 4 + 255) / 256, 256>>>(pw2, W2, DM * DF / 4);

    // GEMM1: inner = tanh(X @ W1^T + b1), rounded to tf32
    gemm_kernel<DM, 1><<<dim3(DF / BN, NROWS / BM), 512, SMEM_BYTES>>>(px, pw1, b1, nullptr);
    // GEMM2: partial row-dots of tanh(inner @ W2^T + b2) with X
    gemm_kernel<DF, 2><<<dim3(DM / BN, NROWS / BM), 512, SMEM_BYTES>>>(pin, pw2, b2, X);
    finalize_kernel<<<(NROWS + 255) / 256, 256>>>((float*)d_out);
}

// round 9
// speedup vs baseline: 1.6193x; 1.6193x over previous
#include <cuda_runtime.h>
#include <cstdint>
#include <cstddef>

#define NROWS 16384
#define DM    1024
#define DF    4096

#define BM 128
#define BN 128
#define BK 32
#define NBUF 3
#define A_BYTES (BM * BK * 4)           // 16384
#define B_BYTES (BN * BK * 4)           // 16384
#define STAGE_BYTES (A_BYTES + B_BYTES) // 32768
#define SM_STAGE_OFF 1024
#define SMEM_BYTES (SM_STAGE_OFF + NBUF * STAGE_BYTES) // 99328

// Scratch (allocation-free rule: __device__ globals)
__device__ float g_x[(size_t)NROWS * DM];
__device__ float g_w1[(size_t)DF * DM];
__device__ float g_w2[(size_t)DM * DF];
__device__ float g_inner[(size_t)NROWS * DF];
__device__ float g_part[(size_t)8 * NROWS];

static __device__ __forceinline__ uint32_t smem_u32(const void* p) {
    uint32_t a;
    asm("{ .reg .u64 t; cvta.to.shared.u64 t, %1; cvt.u32.u64 %0, t; }" : "=r"(a) : "l"(p));
    return a;
}
static __device__ __forceinline__ void cp16(uint32_t dst, const void* src) {
    asm volatile("cp.async.cg.shared.global [%0], [%1], 16;" :: "r"(dst), "l"(src) : "memory");
}
static __device__ __forceinline__ void cp_commit() {
    asm volatile("cp.async.commit_group;" ::: "memory");
}
static __device__ __forceinline__ void cp_wait1() {
    asm volatile("cp.async.wait_group 1;" ::: "memory");
}
static __device__ __forceinline__ float rna_tf32(float v) {
    uint32_t u;
    asm("cvt.rna.tf32.f32 %0, %1;" : "=r"(u) : "f"(v));
    return __uint_as_float(u);
}
static __device__ __forceinline__ void ldsm_x4(uint32_t* r, uint32_t addr) {
    asm volatile("ldmatrix.sync.aligned.m8n8.x4.shared.b16 {%0,%1,%2,%3}, [%4];"
                 : "=r"(r[0]), "=r"(r[1]), "=r"(r[2]), "=r"(r[3]) : "r"(addr));
}
static __device__ __forceinline__ void ldsm_x2(uint32_t* r, uint32_t addr) {
    asm volatile("ldmatrix.sync.aligned.m8n8.x2.shared.b16 {%0,%1}, [%2];"
                 : "=r"(r[0]), "=r"(r[1]) : "r"(addr));
}
static __device__ __forceinline__ void mma_tf32(float* d, const uint32_t* a, const uint32_t* b) {
    asm volatile(
        "mma.sync.aligned.m16n8k8.row.col.f32.tf32.tf32.f32 "
        "{%0,%1,%2,%3}, {%4,%5,%6,%7}, {%8,%9}, {%0,%1,%2,%3};"
        : "+f"(d[0]), "+f"(d[1]), "+f"(d[2]), "+f"(d[3])
        : "r"(a[0]), "r"(a[1]), "r"(a[2]), "r"(a[3]), "r"(b[0]), "r"(b[1]));
}
static __device__ __forceinline__ float fast_tanh(float x) {
    return 1.0f - 2.0f / (1.0f + __expf(2.0f * x));
}

// Load one k-stage (A: BM x BK, B: BN x BK) into swizzled smem via cp.async. 256 threads.
template <int KD>
static __device__ __forceinline__ void load_stage(char* sm, int buf, const float* A,
                                                  const float* W, int m0, int n0,
                                                  int kt, int tid) {
    char* base = sm + SM_STAGE_OFF + buf * STAGE_BYTES;
    const float* asrc = A + (size_t)m0 * KD + (size_t)kt * BK;
    const float* bsrc = W + (size_t)n0 * KD + (size_t)kt * BK;
#pragma unroll
    for (int j = 0; j < 4; j++) {                       // A: 1024 16B chunks
        int i = tid + j * 256;
        int row = i >> 3, jj = i & 7;
        uint32_t woff = row * 32 + ((jj * 4) ^ ((row & 7) * 4));
        cp16(smem_u32(base + woff * 4), asrc + (size_t)row * KD + jj * 4);
    }
#pragma unroll
    for (int j = 0; j < 4; j++) {                       // B: 1024 16B chunks
        int i = tid + j * 256;
        int row = i >> 3, jj = i & 7;
        uint32_t woff = row * 32 + ((jj * 4) ^ ((row & 7) * 4));
        cp16(smem_u32(base + A_BYTES + woff * 4), bsrc + (size_t)row * KD + jj * 4);
    }
    cp_commit();
}

// MODE 1: g_inner = rna_tf32(tanh(A@W^T + bias)); MODE 2: g_part = rowdot(tanh(...), X)
// 8 warps: warp grid 2 (M) x 4 (N); warp tile 64x32.
template <int KD, int MODE>
__global__ void __launch_bounds__(256, 2)
gemm_kernel(const float* __restrict__ A, const float* __restrict__ W,
            const float* __restrict__ bias, const float* __restrict__ X) {
    extern __shared__ char sm[];
    const int tid = threadIdx.x;
    const int lane = tid & 31;
    const int wid = tid >> 5;
    const int wm = wid & 1;        // 2 warps over M (64 rows each)
    const int wn = wid >> 1;       // 4 warps over N (32 cols each)
    const int r = lane >> 2, c = lane & 3;
    const int m0 = blockIdx.y * BM;
    const int n0 = blockIdx.x * BN;
    const int KT = KD / BK;

    if (tid < BN) ((float*)sm)[tid] = bias[n0 + tid];

    // per-lane ldmatrix address components
    const uint32_t aBase = (uint32_t)(wm * 64 + (lane & 15)) * 128;
    const uint32_t bBase = (uint32_t)(wn * 32 + (lane & 7)) * 128;
    const uint32_t swl = (uint32_t)(lane & 7) << 4;
    const uint32_t ahalf4 = (uint32_t)(lane >> 4) << 4;
    const uint32_t bhalf4 = (uint32_t)((lane >> 3) & 1) << 4;

    float acc[4][4][4];
#pragma unroll
    for (int mt = 0; mt < 4; mt++)
#pragma unroll
        for (int nt = 0; nt < 4; nt++)
#pragma unroll
            for (int q = 0; q < 4; q++) acc[mt][nt][q] = 0.0f;

    load_stage<KD>(sm, 0, A, W, m0, n0, 0, tid);
    load_stage<KD>(sm, 1, A, W, m0, n0, 1, tid);

    for (int kt = 0; kt < KT; kt++) {
        cp_wait1();            // stage kt resident
        __syncthreads();       // all warps done reading stage kt-1's buffer
        if (kt + 2 < KT) load_stage<KD>(sm, (kt + 2) % 3, A, W, m0, n0, kt + 2, tid);
        else cp_commit();      // uniform group accounting

        const uint32_t As = smem_u32(sm + SM_STAGE_OFF + (kt % 3) * STAGE_BYTES);
        const uint32_t Bs = As + A_BYTES;
#pragma unroll
        for (int ks = 0; ks < 4; ks++) {
            uint32_t af[4][4], bf[4][2];
            const uint32_t aoff = (((uint32_t)ks << 5) + ahalf4) ^ swl;
            const uint32_t boff = (((uint32_t)ks << 5) + bhalf4) ^ swl;
#pragma unroll
            for (int mt = 0; mt < 4; mt++)
                ldsm_x4(af[mt], As + aBase + (uint32_t)mt * 2048 + aoff);
#pragma unroll
            for (int nt = 0; nt < 4; nt++)
                ldsm_x2(bf[nt], Bs + bBase + (uint32_t)nt * 1024 + boff);
#pragma unroll
            for (int mt = 0; mt < 4; mt++)
#pragma unroll
                for (int nt = 0; nt < 4; nt++)
                    mma_tf32(acc[mt][nt], af[mt], bf[nt]);
        }
    }
    __syncthreads();

    const float* bsm = (const float*)sm;
    if (MODE == 1) {
#pragma unroll
        for (int mt = 0; mt < 4; mt++) {
            int row = m0 + wm * 64 + mt * 16 + r;
#pragma unroll
            for (int nt = 0; nt < 4; nt++) {
                int cl = wn * 32 + nt * 8 + c * 2;
                float2 v0, v1;
                v0.x = rna_tf32(fast_tanh(acc[mt][nt][0] + bsm[cl]));
                v0.y = rna_tf32(fast_tanh(acc[mt][nt][1] + bsm[cl + 1]));
                v1.x = rna_tf32(fast_tanh(acc[mt][nt][2] + bsm[cl]));
                v1.y = rna_tf32(fast_tanh(acc[mt][nt][3] + bsm[cl + 1]));
                *(float2*)(g_inner + (size_t)row * DF + n0 + cl) = v0;
                *(float2*)(g_inner + (size_t)(row + 8) * DF + n0 + cl) = v1;
            }
        }
    } else {
        float rowacc[4][2];
#pragma unroll
        for (int mt = 0; mt < 4; mt++) { rowacc[mt][0] = 0.0f; rowacc[mt][1] = 0.0f; }
#pragma unroll
        for (int mt = 0; mt < 4; mt++) {
            int row = m0 + wm * 64 + mt * 16 + r;
#pragma unroll
            for (int nt = 0; nt < 4; nt++) {
                int cl = wn * 32 + nt * 8 + c * 2;
                float2 x0 = *(const float2*)(X + (size_t)row * DM + n0 + cl);
                float2 x1 = *(const float2*)(X + (size_t)(row + 8) * DM + n0 + cl);
                rowacc[mt][0] += fast_tanh(acc[mt][nt][0] + bsm[cl]) * x0.x
                               + fast_tanh(acc[mt][nt][1] + bsm[cl + 1]) * x0.y;
                rowacc[mt][1] += fast_tanh(acc[mt][nt][2] + bsm[cl]) * x1.x
                               + fast_tanh(acc[mt][nt][3] + bsm[cl + 1]) * x1.y;
            }
        }
#pragma unroll
        for (int mt = 0; mt < 4; mt++)
#pragma unroll
            for (int h = 0; h < 2; h++) {
                float v = rowacc[mt][h];
                v += __shfl_xor_sync(0xFFFFFFFF, v, 1);
                v += __shfl_xor_sync(0xFFFFFFFF, v, 2);
                rowacc[mt][h] = v;
            }
        float* part = (float*)(sm + SM_STAGE_OFF);  // [128][4], stages dead now
        if (c == 0) {
#pragma unroll
            for (int mt = 0; mt < 4; mt++) {
                part[(wm * 64 + mt * 16 + r) * 4 + wn] = rowacc[mt][0];
                part[(wm * 64 + mt * 16 + r + 8) * 4 + wn] = rowacc[mt][1];
            }
        }
        __syncthreads();
        if (tid < 128) {
            float s = part[tid * 4] + part[tid * 4 + 1] + part[tid * 4 + 2] + part[tid * 4 + 3];
            g_part[(size_t)blockIdx.x * NROWS + m0 + tid] = s;
        }
    }
}

__global__ void roundcopy_kernel(float* __restrict__ dst, const float* __restrict__ src, int n4) {
    int i = blockIdx.x * blockDim.x + threadIdx.x;
    if (i < n4) {
        float4 v = ((const float4*)src)[i];
        v.x = rna_tf32(v.x); v.y = rna_tf32(v.y);
        v.z = rna_tf32(v.z); v.w = rna_tf32(v.w);
        ((float4*)dst)[i] = v;
    }
}

__global__ void finalize_kernel(float* __restrict__ out) {
    int i = blockIdx.x * blockDim.x + threadIdx.x;
    if (i < NROWS) {
        float s = 0.0f;
#pragma unroll
        for (int j = 0; j < 8; j++) s += g_part[(size_t)j * NROWS + i];
        out[i] = 1.0f / (1.0f + __expf(-s));
    }
}

extern "C" void kernel_launch(void* const* d_in, const int* in_sizes, int n_in,
                              void* d_out, int out_size) {
    const float* X  = (const float*)d_in[0];
    const float* W1 = (const float*)d_in[1];
    const float* b1 = (const float*)d_in[2];
    const float* W2 = (const float*)d_in[3];
    const float* b2 = (const float*)d_in[4];

    float *px, *pw1, *pw2, *pin;
    cudaGetSymbolAddress((void**)&px,  g_x);
    cudaGetSymbolAddress((void**)&pw1, g_w1);
    cudaGetSymbolAddress((void**)&pw2, g_w2);
    cudaGetSymbolAddress((void**)&pin, g_inner);

    cudaFuncSetAttribute(gemm_kernel<DM, 1>, cudaFuncAttributeMaxDynamicSharedMemorySize, SMEM_BYTES);
    cudaFuncSetAttribute(gemm_kernel<DF, 2>, cudaFuncAttributeMaxDynamicSharedMemorySize, SMEM_BYTES);

    roundcopy_kernel<<<(NROWS * DM / 4 + 255) / 256, 256>>>(px, X, NROWS * DM / 4);
    roundcopy_kernel<<<(DF * DM / 4 + 255) / 256, 256>>>(pw1, W1, DF * DM / 4);
    roundcopy_kernel<<<(DM * DF / 4 + 255) / 256, 256>>>(pw2, W2, DM * DF / 4);

    // GEMM1: inner = tanh(X @ W1^T + b1), rounded to tf32
    gemm_kernel<DM, 1><<<dim3(DF / BN, NROWS / BM), 256, SMEM_BYTES>>>(px, pw1, b1, nullptr);
    // GEMM2: partial row-dots of tanh(inner @ W2^T + b2) with X
    gemm_kernel<DF, 2><<<dim3(DM / BN, NROWS / BM), 256, SMEM_BYTES>>>(pin, pw2, b2, X);
    finalize_kernel<<<(NROWS + 255) / 256, 256>>>((float*)d_out);
}

// round 10
// speedup vs baseline: 3.0016x; 1.8537x over previous
#include <cuda_runtime.h>
#include <cuda_fp16.h>
#include <cstdint>
#include <cstddef>

#define NROWS 16384
#define DM    1024
#define DF    4096

#define BM 128
#define BN 128
#define BK 64                            // fp16: 64 elems = 128B rows
#define NBUF 3
#define A_BYTES (BM * BK * 2)            // 16384
#define B_BYTES (BN * BK * 2)            // 16384
#define STAGE_BYTES (A_BYTES + B_BYTES)  // 32768
#define SM_STAGE_OFF 1024
#define SMEM_BYTES (SM_STAGE_OFF + NBUF * STAGE_BYTES) // 99328

// Scratch (allocation-free rule: __device__ globals)
__device__ __half g_x[(size_t)NROWS * DM];
__device__ __half g_w1[(size_t)DF * DM];
__device__ __half g_w2[(size_t)DM * DF];
__device__ __half g_inner[(size_t)NROWS * DF];
__device__ float  g_part[(size_t)8 * NROWS];

static __device__ __forceinline__ uint32_t smem_u32(const void* p) {
    uint32_t a;
    asm("{ .reg .u64 t; cvta.to.shared.u64 t, %1; cvt.u32.u64 %0, t; }" : "=r"(a) : "l"(p));
    return a;
}
static __device__ __forceinline__ void cp16(uint32_t dst, const void* src) {
    asm volatile("cp.async.cg.shared.global [%0], [%1], 16;" :: "r"(dst), "l"(src) : "memory");
}
static __device__ __forceinline__ void cp_commit() {
    asm volatile("cp.async.commit_group;" ::: "memory");
}
static __device__ __forceinline__ void cp_wait1() {
    asm volatile("cp.async.wait_group 1;" ::: "memory");
}
static __device__ __forceinline__ void ldsm_x4(uint32_t* r, uint32_t addr) {
    asm volatile("ldmatrix.sync.aligned.m8n8.x4.shared.b16 {%0,%1,%2,%3}, [%4];"
                 : "=r"(r[0]), "=r"(r[1]), "=r"(r[2]), "=r"(r[3]) : "r"(addr));
}
static __device__ __forceinline__ void ldsm_x2(uint32_t* r, uint32_t addr) {
    asm volatile("ldmatrix.sync.aligned.m8n8.x2.shared.b16 {%0,%1}, [%2];"
                 : "=r"(r[0]), "=r"(r[1]) : "r"(addr));
}
static __device__ __forceinline__ void mma_f16(float* d, const uint32_t* a, const uint32_t* b) {
    asm volatile(
        "mma.sync.aligned.m16n8k16.row.col.f32.f16.f16.f32 "
        "{%0,%1,%2,%3}, {%4,%5,%6,%7}, {%8,%9}, {%0,%1,%2,%3};"
        : "+f"(d[0]), "+f"(d[1]), "+f"(d[2]), "+f"(d[3])
        : "r"(a[0]), "r"(a[1]), "r"(a[2]), "r"(a[3]), "r"(b[0]), "r"(b[1]));
}
static __device__ __forceinline__ float fast_tanh(float x) {
    return 1.0f - 2.0f / (1.0f + __expf(2.0f * x));
}

// Load one k-stage (A: BM x BK, B: BN x BK fp16) into swizzled smem. 256 threads.
// Row = 128B (8 x 16B chunks), chunk swizzle: chunk ^= (row & 7).
template <int KD>
static __device__ __forceinline__ void load_stage(char* sm, int buf, const __half* A,
                                                  const __half* W, int m0, int n0,
                                                  int kt, int tid) {
    char* base = sm + SM_STAGE_OFF + buf * STAGE_BYTES;
    const __half* asrc = A + (size_t)m0 * KD + (size_t)kt * BK;
    const __half* bsrc = W + (size_t)n0 * KD + (size_t)kt * BK;
#pragma unroll
    for (int j = 0; j < 4; j++) {                       // A: 1024 16B chunks
        int i = tid + j * 256;
        int row = i >> 3, jj = i & 7;
        uint32_t woff = row * 128 + ((jj * 16) ^ ((row & 7) * 16));
        cp16(smem_u32(base + woff), asrc + (size_t)row * KD + jj * 8);
    }
#pragma unroll
    for (int j = 0; j < 4; j++) {                       // B: 1024 16B chunks
        int i = tid + j * 256;
        int row = i >> 3, jj = i & 7;
        uint32_t woff = row * 128 + ((jj * 16) ^ ((row & 7) * 16));
        cp16(smem_u32(base + A_BYTES + woff), bsrc + (size_t)row * KD + jj * 8);
    }
    cp_commit();
}

// MODE 1: g_inner(fp16) = tanh(A@W^T + bias); MODE 2: g_part = rowdot(tanh(...), X)
// 8 warps: warp grid 2 (M) x 4 (N); warp tile 64x32; k16 per MMA, 4 k-steps per kt.
template <int KD, int MODE>
__global__ void __launch_bounds__(256, 2)
gemm_kernel(const __half* __restrict__ A, const __half* __restrict__ W,
            const float* __restrict__ bias, const float* __restrict__ X) {
    extern __shared__ char sm[];
    const int tid = threadIdx.x;
    const int lane = tid & 31;
    const int wid = tid >> 5;
    const int wm = wid & 1;        // 2 warps over M (64 rows each)
    const int wn = wid >> 1;       // 4 warps over N (32 cols each)
    const int r = lane >> 2, c = lane & 3;
    const int m0 = blockIdx.y * BM;
    const int n0 = blockIdx.x * BN;
    const int KT = KD / BK;

    if (tid < BN) ((float*)sm)[tid] = bias[n0 + tid];

    // ldmatrix address components (bytes). A lane row = wm*64+(lane&15); k-half = (lane>>4)*16B.
    const uint32_t aBase = (uint32_t)(wm * 64 + (lane & 15)) * 128;
    const uint32_t bBase = (uint32_t)(wn * 32 + (lane & 7)) * 128;
    const uint32_t swl = (uint32_t)(lane & 7) << 4;
    const uint32_t ahalf = (uint32_t)(lane >> 4) << 4;
    const uint32_t bhalf = (uint32_t)((lane >> 3) & 1) << 4;

    float acc[4][4][4];
#pragma unroll
    for (int mt = 0; mt < 4; mt++)
#pragma unroll
        for (int nt = 0; nt < 4; nt++)
#pragma unroll
            for (int q = 0; q < 4; q++) acc[mt][nt][q] = 0.0f;

    load_stage<KD>(sm, 0, A, W, m0, n0, 0, tid);
    load_stage<KD>(sm, 1, A, W, m0, n0, 1, tid);

    for (int kt = 0; kt < KT; kt++) {
        cp_wait1();            // stage kt resident
        __syncthreads();       // all warps done reading the buffer being overwritten
        if (kt + 2 < KT) load_stage<KD>(sm, (kt + 2) % 3, A, W, m0, n0, kt + 2, tid);
        else cp_commit();      // uniform group accounting

        const uint32_t As = smem_u32(sm + SM_STAGE_OFF + (kt % 3) * STAGE_BYTES);
        const uint32_t Bs = As + A_BYTES;
#pragma unroll
        for (int ks = 0; ks < 4; ks++) {              // each ks = k16 = 32 bytes
            uint32_t af[4][4], bf[4][2];
            const uint32_t aoff = (((uint32_t)ks << 5) + ahalf) ^ swl;
            const uint32_t boff = (((uint32_t)ks << 5) + bhalf) ^ swl;
#pragma unroll
            for (int mt = 0; mt < 4; mt++)
                ldsm_x4(af[mt], As + aBase + (uint32_t)mt * 2048 + aoff);
#pragma unroll
            for (int nt = 0; nt < 4; nt++)
                ldsm_x2(bf[nt], Bs + bBase + (uint32_t)nt * 1024 + boff);
#pragma unroll
            for (int mt = 0; mt < 4; mt++)
#pragma unroll
                for (int nt = 0; nt < 4; nt++)
                    mma_f16(acc[mt][nt], af[mt], bf[nt]);
        }
    }
    __syncthreads();

    const float* bsm = (const float*)sm;
    if (MODE == 1) {
#pragma unroll
        for (int mt = 0; mt < 4; mt++) {
            int row = m0 + wm * 64 + mt * 16 + r;
#pragma unroll
            for (int nt = 0; nt < 4; nt++) {
                int cl = wn * 32 + nt * 8 + c * 2;
                __half2 v0 = __floats2half2_rn(fast_tanh(acc[mt][nt][0] + bsm[cl]),
                                               fast_tanh(acc[mt][nt][1] + bsm[cl + 1]));
                __half2 v1 = __floats2half2_rn(fast_tanh(acc[mt][nt][2] + bsm[cl]),
                                               fast_tanh(acc[mt][nt][3] + bsm[cl + 1]));
                *(__half2*)(g_inner + (size_t)row * DF + n0 + cl) = v0;
                *(__half2*)(g_inner + (size_t)(row + 8) * DF + n0 + cl) = v1;
            }
        }
    } else {
        float rowacc[4][2];
#pragma unroll
        for (int mt = 0; mt < 4; mt++) { rowacc[mt][0] = 0.0f; rowacc[mt][1] = 0.0f; }
#pragma unroll
        for (int mt = 0; mt < 4; mt++) {
            int row = m0 + wm * 64 + mt * 16 + r;
#pragma unroll
            for (int nt = 0; nt < 4; nt++) {
                int cl = wn * 32 + nt * 8 + c * 2;
                float2 x0 = *(const float2*)(X + (size_t)row * DM + n0 + cl);
                float2 x1 = *(const float2*)(X + (size_t)(row + 8) * DM + n0 + cl);
                rowacc[mt][0] += fast_tanh(acc[mt][nt][0] + bsm[cl]) * x0.x
                               + fast_tanh(acc[mt][nt][1] + bsm[cl + 1]) * x0.y;
                rowacc[mt][1] += fast_tanh(acc[mt][nt][2] + bsm[cl]) * x1.x
                               + fast_tanh(acc[mt][nt][3] + bsm[cl + 1]) * x1.y;
            }
        }
#pragma unroll
        for (int mt = 0; mt < 4; mt++)
#pragma unroll
            for (int h = 0; h < 2; h++) {
                float v = rowacc[mt][h];
                v += __shfl_xor_sync(0xFFFFFFFF, v, 1);
                v += __shfl_xor_sync(0xFFFFFFFF, v, 2);
                rowacc[mt][h] = v;
            }
        float* part = (float*)(sm + SM_STAGE_OFF);  // stages dead now
        if (c == 0) {
#pragma unroll
            for (int mt = 0; mt < 4; mt++) {
                part[(wm * 64 + mt * 16 + r) * 4 + wn] = rowacc[mt][0];
                part[(wm * 64 + mt * 16 + r + 8) * 4 + wn] = rowacc[mt][1];
            }
        }
        __syncthreads();
        if (tid < 128) {
            float s = part[tid * 4] + part[tid * 4 + 1] + part[tid * 4 + 2] + part[tid * 4 + 3];
            g_part[(size_t)blockIdx.x * NROWS + m0 + tid] = s;
        }
    }
}

// fp32 -> fp16 (round-to-nearest) conversion, float4 grain
__global__ void h_convert_kernel(__half* __restrict__ dst, const float* __restrict__ src, int n4) {
    int i = blockIdx.x * blockDim.x + threadIdx.x;
    if (i < n4) {
        float4 v = ((const float4*)src)[i];
        __half2 h0 = __floats2half2_rn(v.x, v.y);
        __half2 h1 = __floats2half2_rn(v.z, v.w);
        *(__half2*)(dst + (size_t)i * 4) = h0;
        *(__half2*)(dst + (size_t)i * 4 + 2) = h1;
    }
}

__global__ void finalize_kernel(float* __restrict__ out) {
    int i = blockIdx.x * blockDim.x + threadIdx.x;
    if (i < NROWS) {
        float s = 0.0f;
#pragma unroll
        for (int j = 0; j < 8; j++) s += g_part[(size_t)j * NROWS + i];
        out[i] = 1.0f / (1.0f + __expf(-s));
    }
}

extern "C" void kernel_launch(void* const* d_in, const int* in_sizes, int n_in,
                              void* d_out, int out_size) {
    const float* X  = (const float*)d_in[0];
    const float* W1 = (const float*)d_in[1];
    const float* b1 = (const float*)d_in[2];
    const float* W2 = (const float*)d_in[3];
    const float* b2 = (const float*)d_in[4];

    __half *px, *pw1, *pw2, *pin;
    cudaGetSymbolAddress((void**)&px,  g_x);
    cudaGetSymbolAddress((void**)&pw1, g_w1);
    cudaGetSymbolAddress((void**)&pw2, g_w2);
    cudaGetSymbolAddress((void**)&pin, g_inner);

    cudaFuncSetAttribute(gemm_kernel<DM, 1>, cudaFuncAttributeMaxDynamicSharedMemorySize, SMEM_BYTES);
    cudaFuncSetAttribute(gemm_kernel<DF, 2>, cudaFuncAttributeMaxDynamicSharedMemorySize, SMEM_BYTES);

    h_convert_kernel<<<(NROWS * DM / 4 + 255) / 256, 256>>>(px, X, NROWS * DM / 4);
    h_convert_kernel<<<(DF * DM / 4 + 255) / 256, 256>>>(pw1, W1, DF * DM / 4);
    h_convert_kernel<<<(DM * DF / 4 + 255) / 256, 256>>>(pw2, W2, DM * DF / 4);

    // GEMM1: inner = tanh(X @ W1^T + b1) in fp16
    gemm_kernel<DM, 1><<<dim3(DF / BN, NROWS / BM), 256, SMEM_BYTES>>>(px, pw1, b1, nullptr);
    // GEMM2: partial row-dots of tanh(inner @ W2^T + b2) with X (fp32)
    gemm_kernel<DF, 2><<<dim3(DM / BN, NROWS / BM), 256, SMEM_BYTES>>>(pin, pw2, b2, X);
    finalize_kernel<<<(NROWS + 255) / 256, 256>>>((float*)d_out);
}

// round 13
// speedup vs baseline: 3.0360x; 1.0115x over previous
#include <cuda_runtime.h>
#include <cuda_fp16.h>
#include <cstdint>
#include <cstddef>

#define NROWS 16384
#define DM    1024
#define DF    4096

#define BM 128
#define BN 128
#define BK 64                            // fp16: 64 elems = 128B rows
#define NBUF 3
#define A_BYTES (BM * BK * 2)            // 16384
#define B_BYTES (BN * BK * 2)            // 16384
#define STAGE_BYTES (A_BYTES + B_BYTES)  // 32768
#define SM_STAGE_OFF 1024
#define SMEM_BYTES (SM_STAGE_OFF + NBUF * STAGE_BYTES) // 99328

// Scratch (allocation-free rule: __device__ globals)
__device__ __half g_x[(size_t)NROWS * DM];
__device__ __half g_w1[(size_t)DF * DM];
__device__ __half g_w2[(size_t)DM * DF];
__device__ __half g_inner[(size_t)NROWS * DF];
__device__ float  g_part[(size_t)8 * NROWS];

static __device__ __forceinline__ uint32_t smem_u32(const void* p) {
    uint32_t a;
    asm("{ .reg .u64 t; cvta.to.shared.u64 t, %1; cvt.u32.u64 %0, t; }" : "=r"(a) : "l"(p));
    return a;
}
static __device__ __forceinline__ void cp16(uint32_t dst, const void* src) {
    asm volatile("cp.async.cg.shared.global [%0], [%1], 16;" :: "r"(dst), "l"(src) : "memory");
}
static __device__ __forceinline__ void cp_commit() {
    asm volatile("cp.async.commit_group;" ::: "memory");
}
static __device__ __forceinline__ void cp_wait1() {
    asm volatile("cp.async.wait_group 1;" ::: "memory");
}
static __device__ __forceinline__ void ldsm_x4(uint32_t* r, uint32_t addr) {
    asm volatile("ldmatrix.sync.aligned.m8n8.x4.shared.b16 {%0,%1,%2,%3}, [%4];"
                 : "=r"(r[0]), "=r"(r[1]), "=r"(r[2]), "=r"(r[3]) : "r"(addr));
}
static __device__ __forceinline__ void mma_f16(float* d, const uint32_t* a, const uint32_t* b) {
    asm volatile(
        "mma.sync.aligned.m16n8k16.row.col.f32.f16.f16.f32 "
        "{%0,%1,%2,%3}, {%4,%5,%6,%7}, {%8,%9}, {%0,%1,%2,%3};"
        : "+f"(d[0]), "+f"(d[1]), "+f"(d[2]), "+f"(d[3])
        : "r"(a[0]), "r"(a[1]), "r"(a[2]), "r"(a[3]), "r"(b[0]), "r"(b[1]));
}
static __device__ __forceinline__ float fast_tanh(float x) {
    return 1.0f - 2.0f / (1.0f + __expf(2.0f * x));
}

// Load one k-stage (A: BM x BK, B: BN x BK fp16) into swizzled smem. 256 threads.
// Row = 128B (8 x 16B chunks), chunk swizzle: chunk ^= (row & 7).
template <int KD>
static __device__ __forceinline__ void load_stage(char* sm, int buf, const __half* A,
                                                  const __half* W, int m0, int n0,
                                                  int ktm, int tid) {
    char* base = sm + SM_STAGE_OFF + buf * STAGE_BYTES;
    const __half* asrc = A + (size_t)m0 * KD + (size_t)ktm * BK;
    const __half* bsrc = W + (size_t)n0 * KD + (size_t)ktm * BK;
#pragma unroll
    for (int j = 0; j < 4; j++) {                       // A: 1024 16B chunks
        int i = tid + j * 256;
        int row = i >> 3, jj = i & 7;
        uint32_t woff = row * 128 + ((jj * 16) ^ ((row & 7) * 16));
        cp16(smem_u32(base + woff), asrc + (size_t)row * KD + jj * 8);
    }
#pragma unroll
    for (int j = 0; j < 4; j++) {                       // B: 1024 16B chunks
        int i = tid + j * 256;
        int row = i >> 3, jj = i & 7;
        uint32_t woff = row * 128 + ((jj * 16) ^ ((row & 7) * 16));
        cp16(smem_u32(base + A_BYTES + woff), bsrc + (size_t)row * KD + jj * 8);
    }
    cp_commit();
}

// MODE 1: g_inner(fp16) = tanh(A@W^T + bias); MODE 2: g_part = rowdot(tanh(...), X)
// 8 warps: warp grid 2 (M) x 4 (N); warp tile 64x32; k16 per MMA, 4 k-steps per kt.
// Per-CTA K-phase offset de-phases co-resident CTAs' barriers.
template <int KD, int MODE>
__global__ void __launch_bounds__(256, 2)
gemm_kernel(const __half* __restrict__ A, const __half* __restrict__ W,
            const float* __restrict__ bias, const float* __restrict__ X) {
    extern __shared__ char sm[];
    const int tid = threadIdx.x;
    const int lane = tid & 31;
    const int wid = tid >> 5;
    const int wm = wid & 1;        // 2 warps over M (64 rows each)
    const int wn = wid >> 1;       // 4 warps over N (32 cols each)
    const int r = lane >> 2, c = lane & 3;
    const int m0 = blockIdx.y * BM;
    const int n0 = blockIdx.x * BN;
    const int KT = KD / BK;
    const int bid = blockIdx.x + blockIdx.y * gridDim.x;
    const int off = bid & (KT - 1);   // KT is a power of 2 (16 or 64)

    if (tid < BN) ((float*)sm)[tid] = bias[n0 + tid];

    // ldmatrix address components (bytes).
    const uint32_t aBase = (uint32_t)(wm * 64 + (lane & 15)) * 128;
    // B paired-x4: lane bit4 selects the +8-row (odd-nt) matrix of the pair
    const uint32_t bBase = (uint32_t)(wn * 32 + (lane & 7) + ((lane >> 4) << 3)) * 128;
    const uint32_t swl = (uint32_t)(lane & 7) << 4;
    const uint32_t ahalf = (uint32_t)(lane >> 4) << 4;
    const uint32_t bhalf = (uint32_t)((lane >> 3) & 1) << 4;

    float acc[4][4][4];
#pragma unroll
    for (int mt = 0; mt < 4; mt++)
#pragma unroll
        for (int nt = 0; nt < 4; nt++)
#pragma unroll
            for (int q = 0; q < 4; q++) acc[mt][nt][q] = 0.0f;

    load_stage<KD>(sm, 0, A, W, m0, n0, off, tid);
    load_stage<KD>(sm, 1, A, W, m0, n0, (off + 1) & (KT - 1), tid);

    for (int kt = 0; kt < KT; kt++) {
        cp_wait1();            // stage kt resident
        __syncthreads();       // all warps done reading the buffer being overwritten
        if (kt + 2 < KT)
            load_stage<KD>(sm, (kt + 2) % 3, A, W, m0, n0, (kt + 2 + off) & (KT - 1), tid);
        else cp_commit();      // uniform group accounting

        const uint32_t As = smem_u32(sm + SM_STAGE_OFF + (kt % 3) * STAGE_BYTES);
        const uint32_t Bs = As + A_BYTES;
#pragma unroll
        for (int ks = 0; ks < 4; ks++) {              // each ks = k16 = 32 bytes
            uint32_t af[4][4], bf[2][4];
            const uint32_t aoff = (((uint32_t)ks << 5) + ahalf) ^ swl;
            const uint32_t boff = (((uint32_t)ks << 5) + bhalf) ^ swl;
#pragma unroll
            for (int mt = 0; mt < 4; mt++)
                ldsm_x4(af[mt], As + aBase + (uint32_t)mt * 2048 + aoff);
#pragma unroll
            for (int p = 0; p < 2; p++)               // pair p covers nt=2p, 2p+1
                ldsm_x4(bf[p], Bs + bBase + (uint32_t)p * 2048 + boff);
#pragma unroll
            for (int mt = 0; mt < 4; mt++)
#pragma unroll
                for (int nt = 0; nt < 4; nt++)
                    mma_f16(acc[mt][nt], af[mt], bf[nt >> 1] + (nt & 1) * 2);
        }
    }
    __syncthreads();

    const float* bsm = (const float*)sm;
    if (MODE == 1) {
#pragma unroll
        for (int mt = 0; mt < 4; mt++) {
            int row = m0 + wm * 64 + mt * 16 + r;
#pragma unroll
            for (int nt = 0; nt < 4; nt++) {
                int cl = wn * 32 + nt * 8 + c * 2;
                __half2 v0 = __floats2half2_rn(fast_tanh(acc[mt][nt][0] + bsm[cl]),
                                               fast_tanh(acc[mt][nt][1] + bsm[cl + 1]));
                __half2 v1 = __floats2half2_rn(fast_tanh(acc[mt][nt][2] + bsm[cl]),
                                               fast_tanh(acc[mt][nt][3] + bsm[cl + 1]));
                *(__half2*)(g_inner + (size_t)row * DF + n0 + cl) = v0;
                *(__half2*)(g_inner + (size_t)(row + 8) * DF + n0 + cl) = v1;
            }
        }
    } else {
        float rowacc[4][2];
#pragma unroll
        for (int mt = 0; mt < 4; mt++) { rowacc[mt][0] = 0.0f; rowacc[mt][1] = 0.0f; }
#pragma unroll
        for (int mt = 0; mt < 4; mt++) {
            int row = m0 + wm * 64 + mt * 16 + r;
#pragma unroll
            for (int nt = 0; nt < 4; nt++) {
                int cl = wn * 32 + nt * 8 + c * 2;
                float2 x0 = *(const float2*)(X + (size_t)row * DM + n0 + cl);
                float2 x1 = *(const float2*)(X + (size_t)(row + 8) * DM + n0 + cl);
                rowacc[mt][0] += fast_tanh(acc[mt][nt][0] + bsm[cl]) * x0.x
                               + fast_tanh(acc[mt][nt][1] + bsm[cl + 1]) * x0.y;
                rowacc[mt][1] += fast_tanh(acc[mt][nt][2] + bsm[cl]) * x1.x
                               + fast_tanh(acc[mt][nt][3] + bsm[cl + 1]) * x1.y;
            }
        }
#pragma unroll
        for (int mt = 0; mt < 4; mt++)
#pragma unroll
            for (int h = 0; h < 2; h++) {
                float v = rowacc[mt][h];
                v += __shfl_xor_sync(0xFFFFFFFF, v, 1);
                v += __shfl_xor_sync(0xFFFFFFFF, v, 2);
                rowacc[mt][h] = v;
            }
        float* part = (float*)(sm + SM_STAGE_OFF);  // stages dead now
        if (c == 0) {
#pragma unroll
            for (int mt = 0; mt < 4; mt++) {
                part[(wm * 64 + mt * 16 + r) * 4 + wn] = rowacc[mt][0];
                part[(wm * 64 + mt * 16 + r + 8) * 4 + wn] = rowacc[mt][1];
            }
        }
        __syncthreads();
        if (tid < 128) {
            float s = part[tid * 4] + part[tid * 4 + 1] + part[tid * 4 + 2] + part[tid * 4 + 3];
            g_part[(size_t)blockIdx.x * NROWS + m0 + tid] = s;
        }
    }
}

// fp32 -> fp16 (round-to-nearest) conversion, float4 grain
__global__ void h_convert_kernel(__half* __restrict__ dst, const float* __restrict__ src, int n4) {
    int i = blockIdx.x * blockDim.x + threadIdx.x;
    if (i < n4) {
        float4 v = ((const float4*)src)[i];
        __half2 h0 = __floats2half2_rn(v.x, v.y);
        __half2 h1 = __floats2half2_rn(v.z, v.w);
        *(__half2*)(dst + (size_t)i * 4) = h0;
        *(__half2*)(dst + (size_t)i * 4 + 2) = h1;
    }
}

__global__ void finalize_kernel(float* __restrict__ out) {
    int i = blockIdx.x * blockDim.x + threadIdx.x;
    if (i < NROWS) {
        float s = 0.0f;
#pragma unroll
        for (int j = 0; j < 8; j++) s += g_part[(size_t)j * NROWS + i];
        out[i] = 1.0f / (1.0f + __expf(-s));
    }
}

extern "C" void kernel_launch(void* const* d_in, const int* in_sizes, int n_in,
                              void* d_out, int out_size) {
    const float* X  = (const float*)d_in[0];
    const float* W1 = (const float*)d_in[1];
    const float* b1 = (const float*)d_in[2];
    const float* W2 = (const float*)d_in[3];
    const float* b2 = (const float*)d_in[4];

    __half *px, *pw1, *pw2, *pin;
    cudaGetSymbolAddress((void**)&px,  g_x);
    cudaGetSymbolAddress((void**)&pw1, g_w1);
    cudaGetSymbolAddress((void**)&pw2, g_w2);
    cudaGetSymbolAddress((void**)&pin, g_inner);

    cudaFuncSetAttribute(gemm_kernel<DM, 1>, cudaFuncAttributeMaxDynamicSharedMemorySize, SMEM_BYTES);
    cudaFuncSetAttribute(gemm_kernel<DF, 2>, cudaFuncAttributeMaxDynamicSharedMemorySize, SMEM_BYTES);

    h_convert_kernel<<<(NROWS * DM / 4 + 255) / 256, 256>>>(px, X, NROWS * DM / 4);
    h_convert_kernel<<<(DF * DM / 4 + 255) / 256, 256>>>(pw1, W1, DF * DM / 4);
    h_convert_kernel<<<(DM * DF / 4 + 255) / 256, 256>>>(pw2, W2, DM * DF / 4);

    // GEMM1: inner = tanh(X @ W1^T + b1) in fp16
    gemm_kernel<DM, 1><<<dim3(DF / BN, NROWS / BM), 256, SMEM_BYTES>>>(px, pw1, b1, nullptr);
    // GEMM2: partial row-dots of tanh(inner @ W2^T + b2) with X (fp32)
    gemm_kernel<DF, 2><<<dim3(DM / BN, NROWS / BM), 256, SMEM_BYTES>>>(pin, pw2, b2, X);
    finalize_kernel<<<(NROWS + 255) / 256, 256>>>((float*)d_out);
}